// round 1
// baseline (speedup 1.0000x reference)
#include <cuda_runtime.h>

// Grouping: segment mean-pooling over sorted segment ids.
//   feats:       [B=8, S=8192, H=512] fp32
//   segment_ids: [B=8, S=8192] int32, sorted non-decreasing along S
//   out:         grouped [B, G=1024, H] fp32, then (if room) counts [B, G] as fp32
//
// Sorted ids => each group occupies a contiguous token range [start, end).
// One CTA per (b, g): two lanes binary-search the range, then 128 threads
// stream-sum the contiguous rows (float4, fully coalesced) and scale by 1/count.

#define BB 8
#define SS 8192
#define HH 512
#define GG 1024
#define H4 (HH / 4)  // 128 float4 per row == blockDim.x

__global__ __launch_bounds__(128, 16)
void group_mean_kernel(const float4* __restrict__ feats4,
                       const int* __restrict__ seg,
                       float* __restrict__ out,
                       int write_counts)
{
    const int bg = blockIdx.x;          // 0 .. B*G-1
    const int b  = bg >> 10;            // / G
    const int g  = bg & (GG - 1);       // % G
    const int t  = threadIdx.x;

    __shared__ int sh_bounds[2];
    if (t < 2) {
        // lower_bound of (g + t) in seg[b, :]
        const int* __restrict__ row = seg + b * SS;
        const int target = g + t;
        int lo = 0, hi = SS;
        while (lo < hi) {
            int mid = (lo + hi) >> 1;
            if (row[mid] < target) lo = mid + 1; else hi = mid;
        }
        sh_bounds[t] = lo;
    }
    __syncthreads();

    const int start = sh_bounds[0];
    const int end   = sh_bounds[1];
    const int cnt   = end - start;

    float4 acc = make_float4(0.f, 0.f, 0.f, 0.f);
    const float4* __restrict__ base = feats4 + (size_t)b * SS * H4 + t;

    int s = start;
    // unroll-by-2 to keep >=2 independent LDG.128 in flight per thread
    for (; s + 1 < end; s += 2) {
        float4 v0 = base[(size_t)s * H4];
        float4 v1 = base[(size_t)(s + 1) * H4];
        acc.x += v0.x + v1.x;
        acc.y += v0.y + v1.y;
        acc.z += v0.z + v1.z;
        acc.w += v0.w + v1.w;
    }
    if (s < end) {
        float4 v0 = base[(size_t)s * H4];
        acc.x += v0.x; acc.y += v0.y; acc.z += v0.z; acc.w += v0.w;
    }

    const float inv = (cnt > 0) ? (1.0f / (float)cnt) : 0.0f;
    acc.x *= inv; acc.y *= inv; acc.z *= inv; acc.w *= inv;

    ((float4*)out)[(size_t)bg * H4 + t] = acc;

    if (write_counts && t == 0) {
        out[(size_t)BB * GG * HH + bg] = (float)cnt;
    }
}

extern "C" void kernel_launch(void* const* d_in, const int* in_sizes, int n_in,
                              void* d_out, int out_size)
{
    const float4* feats4 = (const float4*)d_in[0];
    const int*    seg    = (const int*)d_in[1];
    float*        out    = (float*)d_out;

    const int grouped_elems = BB * GG * HH;               // 4,194,304
    const int write_counts  = (out_size >= grouped_elems + BB * GG) ? 1 : 0;

    group_mean_kernel<<<BB * GG, 128>>>(feats4, seg, out, write_counts);
}

// round 2
// speedup vs baseline: 1.1790x; 1.1790x over previous
#include <cuda_runtime.h>

// Grouping: segment mean-pooling over sorted segment ids.
//   feats:       [B=8, S=8192, H=512] fp32
//   segment_ids: [B=8, S=8192] int32, sorted non-decreasing along S
//   out:         grouped [B, G=1024, H] fp32, then (if room) counts [B, G] as fp32
//
// Two kernels:
//   1) boundaries_kernel: one thread per token; adjacent-diff on sorted ids
//      fills starts[b][g] (lower_bound of g) for all g in one pass.
//   2) group_mean_kernel: one CTA per (b,g); reads precomputed [start,end),
//      streams the contiguous rows (float4, MLP=4) and scales by 1/count.

#define BB 8
#define SS 8192
#define HH 512
#define GG 1024
#define H4 (HH / 4)  // 128 float4 per row == blockDim.x

// starts[b][g] = first token index with seg id >= g; starts[b][G] = S
__device__ int g_starts[BB][GG + 1];

__global__ __launch_bounds__(256)
void boundaries_kernel(const int* __restrict__ seg)
{
    const int tid = blockIdx.x * blockDim.x + threadIdx.x;  // 0 .. B*S-1
    const int b = tid >> 13;            // / S
    const int s = tid & (SS - 1);       // % S

    const int cur  = seg[tid];
    const int prev = (s == 0) ? -1 : seg[tid - 1];

    // all group ids in (prev, cur] start at token s
    for (int g = prev + 1; g <= cur; ++g)
        g_starts[b][g] = s;
    // groups beyond the last id in this row are empty: start = S
    if (s == SS - 1) {
        for (int g = cur + 1; g <= GG; ++g)
            g_starts[b][g] = SS;
    }
}

__global__ __launch_bounds__(128, 16)
void group_mean_kernel(const float4* __restrict__ feats4,
                       float* __restrict__ out,
                       int write_counts)
{
    const int bg = blockIdx.x;          // 0 .. B*G-1
    const int b  = bg >> 10;            // / G
    const int g  = bg & (GG - 1);       // % G
    const int t  = threadIdx.x;

    // converged loads (same address across CTA) -> single L2 transaction
    const int start = g_starts[b][g];
    const int end   = g_starts[b][g + 1];
    const int cnt   = end - start;

    float4 acc = make_float4(0.f, 0.f, 0.f, 0.f);
    const float4* __restrict__ base = feats4 + (size_t)b * SS * H4 + t;

    int s = start;
    // 4 independent LDG.128 in flight per thread
    for (; s + 3 < end; s += 4) {
        float4 v0 = base[(size_t)(s + 0) * H4];
        float4 v1 = base[(size_t)(s + 1) * H4];
        float4 v2 = base[(size_t)(s + 2) * H4];
        float4 v3 = base[(size_t)(s + 3) * H4];
        acc.x += (v0.x + v1.x) + (v2.x + v3.x);
        acc.y += (v0.y + v1.y) + (v2.y + v3.y);
        acc.z += (v0.z + v1.z) + (v2.z + v3.z);
        acc.w += (v0.w + v1.w) + (v2.w + v3.w);
    }
    for (; s < end; ++s) {
        float4 v0 = base[(size_t)s * H4];
        acc.x += v0.x; acc.y += v0.y; acc.z += v0.z; acc.w += v0.w;
    }

    const float inv = (cnt > 0) ? (1.0f / (float)cnt) : 0.0f;
    acc.x *= inv; acc.y *= inv; acc.z *= inv; acc.w *= inv;

    ((float4*)out)[(size_t)bg * H4 + t] = acc;

    if (write_counts && t == 0) {
        out[(size_t)BB * GG * HH + bg] = (float)cnt;
    }
}

extern "C" void kernel_launch(void* const* d_in, const int* in_sizes, int n_in,
                              void* d_out, int out_size)
{
    const float4* feats4 = (const float4*)d_in[0];
    const int*    seg    = (const int*)d_in[1];
    float*        out    = (float*)d_out;

    const int grouped_elems = BB * GG * HH;               // 4,194,304
    const int write_counts  = (out_size >= grouped_elems + BB * GG) ? 1 : 0;

    boundaries_kernel<<<(BB * SS) / 256, 256>>>(seg);
    group_mean_kernel<<<BB * GG, 128>>>(feats4, out, write_counts);
}